// round 6
// baseline (speedup 1.0000x reference)
#include <cuda_runtime.h>
#include <cuda_bf16.h>
#include <stdint.h>

// Problem constants (fixed by the reference: T=8, L=2,000,000, B=16,384)
#define T_TABLES 8
#define L_PER_TABLE 2000000
#define B_BATCH 16384           // power of two -> shift/mask indexing
#define B_LOG2 14
#define TL (T_TABLES * L_PER_TABLE)          // 16,000,000
#define N4 (TL / 4)                          // 4,000,000
#define OFF_OUT (T_TABLES * B_BATCH + 1)     // 131,073
#define OFF_IN_STRIDE (B_BATCH + 1)          // 16,385

// out layout (float32):
//   [0, TL)                        : float(combined_indices)        (16B aligned)
//   [TL, TL+OFF_OUT)               : float(combined_offsets)
//   [TL+OFF_OUT, TL+OFF_OUT+TL)    : combined_weights  (starts at odd index!)
//
// Weights output base = TL+OFF_OUT = 16,131,073  (== 1 mod 4).
// Aligned store base  = 16,131,072 (the LAST offsets slot) -> shifted stores.
#define W_OUT_START   (TL + OFF_OUT)         // 16,131,073
#define W_ALIGN_BASE  (W_OUT_START - 1)      // 16,131,072 (16B aligned)
#define W_STORES      N4                     // 4,000,000 float4 stores
// store k writes out[W_ALIGN_BASE+4k .. +3] = { w[4k-1], w[4k], w[4k+1], w[4k+2] }
// covered weights: w[0 .. 15,999,998]; tail w[15,999,999] fixed in kernel B.

#define THREADS 256
#define BIG_BLOCKS ((2 * N4 + THREADS - 1) / THREADS)   // 31,250
#define OFF_BLOCKS ((OFF_OUT + THREADS - 1) / THREADS)  // 513

// ---------------- Kernel A: the two 64MB streaming regions ----------------
__global__ void __launch_bounds__(THREADS)
tbe_big_kernel(const int4* __restrict__ idx4,
               const float4* __restrict__ w4,
               float* __restrict__ out) {
    long long i = (long long)blockIdx.x * THREADS + threadIdx.x;

    if (i < N4) {
        // indices -> float, fully aligned 16B load/store
        int4 v = idx4[i];
        ((float4*)out)[i] =
            make_float4((float)v.x, (float)v.y, (float)v.z, (float)v.w);
    } else if (i < 2LL * N4) {
        long long k = i - N4;
        float4 b = w4[k];                       // w[4k .. 4k+3]
        float prev;
        if (k > 0) {
            prev = w4[k - 1].w;                 // w[4k-1]; same line as thread k-1 -> L1 hit
        } else {
            prev = 0.0f;                        // slot overwritten by kernel B
        }
        float4* wout = (float4*)(out + (long long)W_ALIGN_BASE);
        wout[k] = make_float4(prev, b.x, b.y, b.z);  // aligned STG.128
    }
}

// ---------------- Kernel B: offsets region + fixups (runs after A) ----------------
__global__ void __launch_bounds__(THREADS)
tbe_offsets_kernel(const int* __restrict__ offs,
                   const float* __restrict__ w,
                   float* __restrict__ out) {
    int j = blockIdx.x * THREADS + threadIdx.x;
    if (j < OFF_OUT - 1) {
        int t = j >> B_LOG2;
        int r = j & (B_BATCH - 1);
        out[TL + j] = (float)(offs[t * OFF_IN_STRIDE + r] + t * L_PER_TABLE);
    } else if (j == OFF_OUT - 1) {
        // last combined_offset = T*L (this is the slot kernel A "pre-wrote")
        out[TL + j] = (float)TL;
        // tail weight element not covered by shifted stores
        out[(long long)W_OUT_START + (TL - 1)] = w[TL - 1];
    }
}

extern "C" void kernel_launch(void* const* d_in, const int* in_sizes, int n_in,
                              void* d_out, int out_size) {
    const int* indices = (const int*)d_in[0];       // [T, L] int32
    const int* offsets = (const int*)d_in[1];       // [T, B+1] int32
    const float* weights = (const float*)d_in[2];   // [T, L] float32
    float* out = (float*)d_out;

    tbe_big_kernel<<<BIG_BLOCKS, THREADS>>>(
        (const int4*)indices, (const float4*)weights, out);
    // Same stream -> ordered after kernel A; overwrites the shifted slot.
    tbe_offsets_kernel<<<OFF_BLOCKS, THREADS>>>(offsets, weights, out);
}

// round 7
// speedup vs baseline: 1.0375x; 1.0375x over previous
#include <cuda_runtime.h>
#include <cuda_bf16.h>
#include <stdint.h>

// Problem constants (fixed by the reference: T=8, L=2,000,000, B=16,384)
#define T_TABLES 8
#define L_PER_TABLE 2000000
#define B_BATCH 16384           // power of two -> shift/mask indexing
#define B_LOG2 14
#define TL (T_TABLES * L_PER_TABLE)          // 16,000,000
#define N4 (TL / 4)                          // 4,000,000
#define OFF_OUT (T_TABLES * B_BATCH + 1)     // 131,073
#define OFF_IN_STRIDE (B_BATCH + 1)          // 16,385

// out layout (float32):
//   [0, TL)                        : float(combined_indices)        (16B aligned)
//   [TL, TL+OFF_OUT)               : float(combined_offsets)
//   [TL+OFF_OUT, TL+OFF_OUT+TL)    : combined_weights  (starts at index ==1 mod 4)
//
// Weights output base = TL+OFF_OUT = 16,131,073 (odd) -> stores shifted down by 1:
//   store k writes out[W_ALIGN_BASE+4k .. +3] = { w[4k-1], w[4k], w[4k+1], w[4k+2] }
// The k=0 slot out[W_ALIGN_BASE] is combined_offsets' LAST element == (float)TL,
// written directly by the k=0 thread (constant, no ordering needed).
// Tail w[TL-1] written by the k=N4-1 thread.
#define W_OUT_START   (TL + OFF_OUT)         // 16,131,073
#define W_ALIGN_BASE  (W_OUT_START - 1)      // 16,131,072 (16B aligned)

#define THREADS 256
#define BIG_BLOCKS ((2 * N4) / THREADS)                   // 31,250 (exact)
#define OFF_BODY   (OFF_OUT - 1)                          // 131,072
#define OFF_BLOCKS (OFF_BODY / THREADS)                   // 512 (exact)
#define TOTAL_BLOCKS (BIG_BLOCKS + OFF_BLOCKS)

__global__ void __launch_bounds__(THREADS)
tbe_fused_kernel(const int4* __restrict__ idx4,
                 const int* __restrict__ offs,
                 const float4* __restrict__ w4,
                 const float* __restrict__ w,
                 float* __restrict__ out) {
    long long i = (long long)blockIdx.x * THREADS + threadIdx.x;

    if (i < N4) {
        // ---- indices -> float, aligned 16B load/store ----
        int4 v = idx4[i];
        ((float4*)out)[i] =
            make_float4((float)v.x, (float)v.y, (float)v.z, (float)v.w);
    } else if (i < 2LL * N4) {
        // ---- weights copy, store-shifted by one float ----
        long long k = i - N4;
        float4 b = w4[k];                         // w[4k .. 4k+3]
        // previous element w[4k-1]: from lane-1's b.w via shuffle;
        // lane 0 (k multiple of 32 within warp) loads it as a scalar.
        int lane = threadIdx.x & 31;
        float prev = __shfl_up_sync(0xFFFFFFFFu, b.w, 1);
        if (lane == 0) {
            prev = (k > 0) ? w[4 * k - 1] : (float)TL;  // k==0: combined_offsets last
        }
        float4* wout = (float4*)(out + (long long)W_ALIGN_BASE);
        wout[k] = make_float4(prev, b.x, b.y, b.z);     // aligned STG.128
        if (k == N4 - 1) {
            // tail element not covered by shifted stores
            out[(long long)W_OUT_START + (TL - 1)] = w[TL - 1];
        }
    } else {
        // ---- combined_offsets body (last element handled by weights k=0) ----
        int j = (int)(i - 2LL * N4);
        if (j < OFF_BODY) {
            int t = j >> B_LOG2;
            int r = j & (B_BATCH - 1);
            out[TL + j] = (float)(offs[t * OFF_IN_STRIDE + r] + t * L_PER_TABLE);
        }
    }
}

extern "C" void kernel_launch(void* const* d_in, const int* in_sizes, int n_in,
                              void* d_out, int out_size) {
    const int* indices = (const int*)d_in[0];       // [T, L] int32
    const int* offsets = (const int*)d_in[1];       // [T, B+1] int32
    const float* weights = (const float*)d_in[2];   // [T, L] float32
    float* out = (float*)d_out;

    tbe_fused_kernel<<<TOTAL_BLOCKS, THREADS>>>(
        (const int4*)indices, offsets, (const float4*)weights, weights, out);
}